// round 1
// baseline (speedup 1.0000x reference)
#include <cuda_runtime.h>
#include <cuda_bf16.h>
#include <math.h>

#define BB 2048
#define NN 32
#define VV 10
#define HH 256
#define H3 768
#define ZZ 64
#define TB 16
#define NCTA (BB / TB)   // 128

// Scratch (no allocations allowed): gm history + transposed adjacency
__device__ float g_gm[BB * NN * HH];      // 64 MB
__device__ float g_adjt[BB * NN * NN];    // 8 MB : adjt[b][v][n] = adj[b][n][v]

__device__ __forceinline__ float sigmoidf_(float x) {
    return 1.0f / (1.0f + expf(-x));
}

__global__ void transpose_adj_kernel(const float* __restrict__ adj) {
    int idx = blockIdx.x * blockDim.x + threadIdx.x;
    if (idx < BB * NN * NN) {
        int b = idx >> 10;          // / (N*N)
        int r = idx & 1023;
        int v = r >> 5;
        int n = r & 31;
        g_adjt[idx] = adj[(b << 10) + (n << 5) + v];
    }
}

__global__ __launch_bounds__(256, 1) void logicvae_main(
    const int*   __restrict__ node_types,
    const float* __restrict__ w_ih,
    const float* __restrict__ w_hh,
    const float* __restrict__ b_ih,
    const float* __restrict__ b_hh,
    const float* __restrict__ w_gate,
    const float* __restrict__ b_gate,
    const float* __restrict__ w_map,
    const float* __restrict__ w_mu,
    const float* __restrict__ b_mu,
    const float* __restrict__ w_std,
    const float* __restrict__ b_std,
    float* __restrict__ out)
{
    __shared__ float agg_s[HH * TB];   // [k][b] layout, 16 KB
    __shared__ float h_s[HH * TB];     // [k][b] layout, 16 KB
    __shared__ float adj_s[TB * NN];   // adj col v for this CTA's batches
    __shared__ int   nt_s[TB];

    const int tid = threadIdx.x;       // 0..255 == hidden unit j
    const int j   = tid;
    const int b0  = blockIdx.x * TB;

    // Per-column biases (each thread owns hidden unit j)
    const float bihr = b_ih[j], bihz = b_ih[j + HH], bihn = b_ih[j + 2 * HH];
    const float bhhr = b_hh[j], bhhz = b_hh[j + HH], bhhn = b_hh[j + 2 * HH];
    const float bg   = b_gate[j];

    const float4* ag4 = (const float4*)agg_s;
    const float4* h4  = (const float4*)h_s;

    for (int v = 0; v < NN; v++) {
        // ---- Load adj column v (transposed: coalesced over n) + node types ----
        #pragma unroll
        for (int idx = tid; idx < TB * NN; idx += 256) {
            int b = idx >> 5, n = idx & 31;
            adj_s[idx] = g_adjt[((b0 + b) << 10) + (v << 5) + n];
        }
        if (tid < TB) nt_s[tid] = node_types[(b0 + tid) * NN + v];

        // ---- Phase A: agg[b][j] = sum_{n<v} adj[b,n,v] * gm[b,n,j] ----
        float acc[TB];
        #pragma unroll
        for (int b = 0; b < TB; b++) acc[b] = 0.0f;

        __syncthreads();   // adj_s/nt_s visible; also fences last step's g_gm writes

        for (int n = 0; n < v; n++) {
            #pragma unroll
            for (int b = 0; b < TB; b++) {
                acc[b] = fmaf(adj_s[b * NN + n],
                              g_gm[(size_t)((b0 + b) * NN + n) * HH + j],
                              acc[b]);
            }
        }
        {
            float4* a4w = (float4*)(agg_s + tid * TB);
            a4w[0] = make_float4(acc[0],  acc[1],  acc[2],  acc[3]);
            a4w[1] = make_float4(acc[4],  acc[5],  acc[6],  acc[7]);
            a4w[2] = make_float4(acc[8],  acc[9],  acc[10], acc[11]);
            a4w[3] = make_float4(acc[12], acc[13], acc[14], acc[15]);
        }
        __syncthreads();

        // ---- Phase B: gh = agg @ w_hh  (thread j owns columns j, j+256, j+512) ----
        float ar[TB], az[TB], an[TB];
        #pragma unroll
        for (int b = 0; b < TB; b++) { ar[b] = 0.f; az[b] = 0.f; an[b] = 0.f; }

        #pragma unroll 2
        for (int k = 0; k < HH; k++) {
            const float wr = w_hh[k * H3 + j];
            const float wz = w_hh[k * H3 + HH + j];
            const float wn = w_hh[k * H3 + 2 * HH + j];
            const float4 q0 = ag4[4 * k + 0];
            const float4 q1 = ag4[4 * k + 1];
            const float4 q2 = ag4[4 * k + 2];
            const float4 q3 = ag4[4 * k + 3];
            float av[TB];
            av[0]=q0.x;  av[1]=q0.y;  av[2]=q0.z;  av[3]=q0.w;
            av[4]=q1.x;  av[5]=q1.y;  av[6]=q1.z;  av[7]=q1.w;
            av[8]=q2.x;  av[9]=q2.y;  av[10]=q2.z; av[11]=q2.w;
            av[12]=q3.x; av[13]=q3.y; av[14]=q3.z; av[15]=q3.w;
            #pragma unroll
            for (int b = 0; b < TB; b++) {
                ar[b] = fmaf(av[b], wr, ar[b]);
                az[b] = fmaf(av[b], wz, az[b]);
                an[b] = fmaf(av[b], wn, an[b]);
            }
        }

        // ---- GRU elementwise; x@w_ih is a row lookup (one-hot input) ----
        #pragma unroll
        for (int b = 0; b < TB; b++) {
            const int t = nt_s[b];
            const float gir = w_ih[t * H3 + j]            + bihr;
            const float giz = w_ih[t * H3 + HH + j]       + bihz;
            const float gin = w_ih[t * H3 + 2 * HH + j]   + bihn;
            const float r   = sigmoidf_(gir + ar[b] + bhhr);
            const float z   = sigmoidf_(giz + az[b] + bhhz);
            const float nn_ = tanhf(gin + r * (an[b] + bhhn));
            const float hnew = (1.0f - z) * nn_ + z * acc[b];   // acc[b] == agg
            h_s[j * TB + b] = hnew;
        }
        __syncthreads();

        if (v < NN - 1) {
            // ---- Phase C: gm_v = sigmoid(h@w_gate+bg) * (h@w_map) ----
            float ag[TB], am[TB];
            #pragma unroll
            for (int b = 0; b < TB; b++) { ag[b] = 0.f; am[b] = 0.f; }

            #pragma unroll 2
            for (int k = 0; k < HH; k++) {
                const float wg = w_gate[k * HH + j];
                const float wm = w_map[k * HH + j];
                const float4 q0 = h4[4 * k + 0];
                const float4 q1 = h4[4 * k + 1];
                const float4 q2 = h4[4 * k + 2];
                const float4 q3 = h4[4 * k + 3];
                float hv[TB];
                hv[0]=q0.x;  hv[1]=q0.y;  hv[2]=q0.z;  hv[3]=q0.w;
                hv[4]=q1.x;  hv[5]=q1.y;  hv[6]=q1.z;  hv[7]=q1.w;
                hv[8]=q2.x;  hv[9]=q2.y;  hv[10]=q2.z; hv[11]=q2.w;
                hv[12]=q3.x; hv[13]=q3.y; hv[14]=q3.z; hv[15]=q3.w;
                #pragma unroll
                for (int b = 0; b < TB; b++) {
                    ag[b] = fmaf(hv[b], wg, ag[b]);
                    am[b] = fmaf(hv[b], wm, am[b]);
                }
            }
            #pragma unroll
            for (int b = 0; b < TB; b++) {
                const float g = sigmoidf_(ag[b] + bg);
                g_gm[(size_t)((b0 + b) * NN + v) * HH + j] = g * am[b];
            }
        } else {
            // ---- Final step: hg = h_31 ; mu = hg@w_mu+b_mu ; sigma = hg@w_std+b_std ----
            const int z   = tid & 63;    // 0..63
            const int grp = tid >> 6;    // 0..3
            float am[4] = {0.f, 0.f, 0.f, 0.f};
            float as[4] = {0.f, 0.f, 0.f, 0.f};
            #pragma unroll 4
            for (int k = 0; k < HH; k++) {
                const float wm = w_mu[k * ZZ + z];
                const float ws = w_std[k * ZZ + z];
                #pragma unroll
                for (int i = 0; i < 4; i++) {
                    const float hv = h_s[k * TB + grp + i * 4];
                    am[i] = fmaf(hv, wm, am[i]);
                    as[i] = fmaf(hv, ws, as[i]);
                }
            }
            const float bmu = b_mu[z], bstd = b_std[z];
            #pragma unroll
            for (int i = 0; i < 4; i++) {
                const int b = grp + i * 4;
                out[(size_t)(b0 + b) * ZZ + z]             = am[i] + bmu;
                out[(size_t)BB * ZZ + (size_t)(b0 + b) * ZZ + z] = as[i] + bstd;
            }
        }
    }
}

extern "C" void kernel_launch(void* const* d_in, const int* in_sizes, int n_in,
                              void* d_out, int out_size) {
    const float* adj        = (const float*)d_in[0];
    const int*   node_types = (const int*)  d_in[1];
    const float* w_ih       = (const float*)d_in[2];
    const float* w_hh       = (const float*)d_in[3];
    const float* b_ih       = (const float*)d_in[4];
    const float* b_hh       = (const float*)d_in[5];
    const float* w_gate     = (const float*)d_in[6];
    const float* b_gate     = (const float*)d_in[7];
    const float* w_map      = (const float*)d_in[8];
    const float* w_mu       = (const float*)d_in[9];
    const float* b_mu       = (const float*)d_in[10];
    const float* w_std      = (const float*)d_in[11];
    const float* w_std2     = (const float*)d_in[12];
    float* out = (float*)d_out;

    // Transpose adjacency once per launch (deterministic, graph-capturable)
    transpose_adj_kernel<<<(BB * NN * NN + 255) / 256, 256>>>(adj);

    logicvae_main<<<NCTA, 256>>>(node_types, w_ih, w_hh, b_ih, b_hh,
                                 w_gate, b_gate, w_map,
                                 w_mu, b_mu, w_std, w_std2, out);
}

// round 2
// speedup vs baseline: 1.6079x; 1.6079x over previous
#include <cuda_runtime.h>
#include <cuda_bf16.h>
#include <math.h>

#define BB 2048
#define NN 32
#define HH 256
#define H3 768
#define ZZ 64
#define TB 16
#define NCTA (BB / TB)   // 128
#define PAD 20           // smem row stride (floats): 4-way instead of 16-way write conflicts

// Scratch (no allocations allowed): gm history + transposed adjacency
__device__ float g_gm[BB * NN * HH];      // 64 MB
__device__ float g_adjt[BB * NN * NN];    // 8 MB : adjt[b][v][n] = adj[b][n][v]

typedef unsigned long long u64;

__device__ __forceinline__ u64 pack2(float x) {
    u64 r; asm("mov.b64 %0, {%1, %1};" : "=l"(r) : "f"(x)); return r;
}
__device__ __forceinline__ void ffma2(u64 &d, u64 a, u64 b) {
    asm("fma.rn.f32x2 %0, %1, %2, %0;" : "+l"(d) : "l"(a), "l"(b));
}
__device__ __forceinline__ float2 unpack2(u64 a) {
    float2 f; asm("mov.b64 {%0, %1}, %2;" : "=f"(f.x), "=f"(f.y) : "l"(a)); return f;
}
__device__ __forceinline__ float fsig(float x) {
    return __fdividef(1.0f, 1.0f + __expf(-x));
}
__device__ __forceinline__ float ftanh(float x) {
    float y; asm("tanh.approx.f32 %0, %1;" : "=f"(y) : "f"(x)); return y;
}

__global__ void transpose_adj_kernel(const float* __restrict__ adj) {
    int idx = blockIdx.x * blockDim.x + threadIdx.x;
    if (idx < BB * NN * NN) {
        int b = idx >> 10;
        int r = idx & 1023;
        int v = r >> 5;
        int n = r & 31;
        g_adjt[idx] = adj[(b << 10) + (n << 5) + v];
    }
}

__global__ __launch_bounds__(512, 1) void logicvae_main(
    const int*   __restrict__ node_types,
    const float* __restrict__ w_ih,
    const float* __restrict__ w_hh,
    const float* __restrict__ b_ih,
    const float* __restrict__ b_hh,
    const float* __restrict__ w_gate,
    const float* __restrict__ b_gate,
    const float* __restrict__ w_map,
    const float* __restrict__ w_mu,
    const float* __restrict__ b_mu,
    const float* __restrict__ w_std,
    const float* __restrict__ b_std,
    float* __restrict__ out)
{
    __shared__ float agg_s[HH * PAD];   // [k][b] padded, 20 KB
    __shared__ float h_s[HH * PAD];     // [k][b] padded, 20 KB
    __shared__ float adj_s[TB * NN];
    __shared__ int   nt_s[TB];

    const int tid  = threadIdx.x;       // 0..511
    const int j    = tid & 255;         // hidden unit
    const int half = tid >> 8;          // 0: batches 0-7, 1: batches 8-15
    const int hb   = half * 8;
    const int b0   = blockIdx.x * TB;

    const float bihr = b_ih[j], bihz = b_ih[j + HH], bihn = b_ih[j + 2 * HH];
    const float bhhr = b_hh[j], bhhz = b_hh[j + HH], bhhn = b_hh[j + 2 * HH];
    const float bg   = b_gate[j];

    for (int v = 0; v < NN; v++) {
        // ---- adj column v (transposed: coalesced over n) + node types ----
        {
            int b = tid >> 5, n = tid & 31;   // 512 entries, 512 threads
            adj_s[tid] = g_adjt[((b0 + b) << 10) + (v << 5) + n];
        }
        if (tid < TB) nt_s[tid] = node_types[(b0 + tid) * NN + v];

        float acc[8];
        #pragma unroll
        for (int b = 0; b < 8; b++) acc[b] = 0.0f;

        __syncthreads();   // adj_s/nt_s visible; fences last step's g_gm/h_s

        // ---- Phase A: agg[b][j] = sum_{n<v} adj[b,n,v] * gm[b,n,j] ----
        for (int n = 0; n < v; n++) {
            float a[8];
            #pragma unroll
            for (int b = 0; b < 8; b++) a[b] = adj_s[(hb + b) * NN + n];
            float s = a[0]+a[1]+a[2]+a[3]+a[4]+a[5]+a[6]+a[7];
            if (s != 0.0f) {   // warp-uniform (adj depends on b,n only)
                #pragma unroll
                for (int b = 0; b < 8; b++) {
                    acc[b] = fmaf(a[b],
                                  g_gm[(size_t)((b0 + hb + b) * NN + n) * HH + j],
                                  acc[b]);
                }
            }
        }
        {
            float4* a4 = (float4*)(agg_s + j * PAD + hb);
            a4[0] = make_float4(acc[0], acc[1], acc[2], acc[3]);
            a4[1] = make_float4(acc[4], acc[5], acc[6], acc[7]);
        }
        __syncthreads();

        // ---- Phase B: gh = agg @ w_hh  (packed f32x2, pairs of batches) ----
        u64 ar2[4], az2[4], an2[4];
        #pragma unroll
        for (int i = 0; i < 4; i++) { ar2[i] = 0ull; az2[i] = 0ull; an2[i] = 0ull; }

        const float* whc = w_hh + j;
        #pragma unroll 4
        for (int k = 0; k < HH; k++) {
            const float wr = whc[k * H3];
            const float wz = whc[k * H3 + HH];
            const float wn = whc[k * H3 + 2 * HH];
            const u64 wr2 = pack2(wr), wz2 = pack2(wz), wn2 = pack2(wn);
            const ulonglong2* p = (const ulonglong2*)(agg_s + k * PAD + hb);
            const ulonglong2 q0 = p[0], q1 = p[1];
            ffma2(ar2[0], q0.x, wr2); ffma2(ar2[1], q0.y, wr2);
            ffma2(ar2[2], q1.x, wr2); ffma2(ar2[3], q1.y, wr2);
            ffma2(az2[0], q0.x, wz2); ffma2(az2[1], q0.y, wz2);
            ffma2(az2[2], q1.x, wz2); ffma2(az2[3], q1.y, wz2);
            ffma2(an2[0], q0.x, wn2); ffma2(an2[1], q0.y, wn2);
            ffma2(an2[2], q1.x, wn2); ffma2(an2[3], q1.y, wn2);
        }

        // ---- GRU elementwise; x@w_ih is a row lookup (one-hot input) ----
        {
            float hval[8];
            #pragma unroll
            for (int i = 0; i < 4; i++) {
                const float2 fr = unpack2(ar2[i]);
                const float2 fz = unpack2(az2[i]);
                const float2 fn = unpack2(an2[i]);
                #pragma unroll
                for (int u = 0; u < 2; u++) {
                    const int b = 2 * i + u;
                    const int t = nt_s[hb + b];
                    const float gir = w_ih[t * H3 + j]          + bihr;
                    const float giz = w_ih[t * H3 + HH + j]     + bihz;
                    const float gin = w_ih[t * H3 + 2 * HH + j] + bihn;
                    const float arv = u ? fr.y : fr.x;
                    const float azv = u ? fz.y : fz.x;
                    const float anv = u ? fn.y : fn.x;
                    const float r   = fsig(gir + arv + bhhr);
                    const float z   = fsig(giz + azv + bhhz);
                    const float nn_ = ftanh(gin + r * (anv + bhhn));
                    hval[b] = (1.0f - z) * nn_ + z * acc[b];   // acc == agg
                }
            }
            float4* h4w = (float4*)(h_s + j * PAD + hb);
            h4w[0] = make_float4(hval[0], hval[1], hval[2], hval[3]);
            h4w[1] = make_float4(hval[4], hval[5], hval[6], hval[7]);
        }
        __syncthreads();

        if (v < NN - 1) {
            // ---- Phase C: gm_v = sigmoid(h@w_gate+bg) * (h@w_map) ----
            u64 ag2[4], am2[4];
            #pragma unroll
            for (int i = 0; i < 4; i++) { ag2[i] = 0ull; am2[i] = 0ull; }

            #pragma unroll 4
            for (int k = 0; k < HH; k++) {
                const float wg = w_gate[k * HH + j];
                const float wm = w_map[k * HH + j];
                const u64 wg2 = pack2(wg), wm2 = pack2(wm);
                const ulonglong2* p = (const ulonglong2*)(h_s + k * PAD + hb);
                const ulonglong2 q0 = p[0], q1 = p[1];
                ffma2(ag2[0], q0.x, wg2); ffma2(ag2[1], q0.y, wg2);
                ffma2(ag2[2], q1.x, wg2); ffma2(ag2[3], q1.y, wg2);
                ffma2(am2[0], q0.x, wm2); ffma2(am2[1], q0.y, wm2);
                ffma2(am2[2], q1.x, wm2); ffma2(am2[3], q1.y, wm2);
            }
            #pragma unroll
            for (int i = 0; i < 4; i++) {
                const float2 fg = unpack2(ag2[i]);
                const float2 fm = unpack2(am2[i]);
                const int ba = hb + 2 * i;
                g_gm[(size_t)((b0 + ba)     * NN + v) * HH + j] = fsig(fg.x + bg) * fm.x;
                g_gm[(size_t)((b0 + ba + 1) * NN + v) * HH + j] = fsig(fg.y + bg) * fm.y;
            }
        } else {
            // ---- Final: mu = h31@w_mu+b_mu ; sigma = h31@w_std+b_std ----
            const int z   = tid & 63;     // 0..63
            const int grp = tid >> 6;     // 0..7, warp-uniform
            const int bA  = 2 * grp, bB = 2 * grp + 1;
            float am0 = 0.f, am1 = 0.f, as0 = 0.f, as1 = 0.f;
            #pragma unroll 4
            for (int k = 0; k < HH; k++) {
                const float wm = w_mu[k * ZZ + z];
                const float ws = w_std[k * ZZ + z];
                const float h0 = h_s[k * PAD + bA];   // broadcast within warp
                const float h1 = h_s[k * PAD + bB];
                am0 = fmaf(h0, wm, am0); am1 = fmaf(h1, wm, am1);
                as0 = fmaf(h0, ws, as0); as1 = fmaf(h1, ws, as1);
            }
            const float bmu = b_mu[z], bstd = b_std[z];
            out[(size_t)(b0 + bA) * ZZ + z] = am0 + bmu;
            out[(size_t)(b0 + bB) * ZZ + z] = am1 + bmu;
            out[(size_t)BB * ZZ + (size_t)(b0 + bA) * ZZ + z] = as0 + bstd;
            out[(size_t)BB * ZZ + (size_t)(b0 + bB) * ZZ + z] = as1 + bstd;
        }
    }
}

extern "C" void kernel_launch(void* const* d_in, const int* in_sizes, int n_in,
                              void* d_out, int out_size) {
    const float* adj        = (const float*)d_in[0];
    const int*   node_types = (const int*)  d_in[1];
    const float* w_ih       = (const float*)d_in[2];
    const float* w_hh       = (const float*)d_in[3];
    const float* b_ih       = (const float*)d_in[4];
    const float* b_hh       = (const float*)d_in[5];
    const float* w_gate     = (const float*)d_in[6];
    const float* b_gate     = (const float*)d_in[7];
    const float* w_map      = (const float*)d_in[8];
    const float* w_mu       = (const float*)d_in[9];
    const float* b_mu       = (const float*)d_in[10];
    const float* w_std      = (const float*)d_in[11];
    const float* b_std      = (const float*)d_in[12];
    float* out = (float*)d_out;

    transpose_adj_kernel<<<(BB * NN * NN + 255) / 256, 256>>>(adj);

    logicvae_main<<<NCTA, 512>>>(node_types, w_ih, w_hh, b_ih, b_hh,
                                 w_gate, b_gate, w_map,
                                 w_mu, b_mu, w_std, b_std, out);
}

// round 5
// speedup vs baseline: 1.9330x; 1.2022x over previous
#include <cuda_runtime.h>
#include <cuda_bf16.h>
#include <cstdint>
#include <math.h>

#define BB 2048
#define NN 32
#define HH 256
#define H3 768
#define ZZ 64
#define TB 16
#define NCTA (BB / TB)   // 128
#define PAD 20
#define CHUNK 16
#define NCH (HH / CHUNK)            // 16 chunks
#define WB_FLOATS (CHUNK * H3)      // 12288
#define WB_BYTES  (WB_FLOATS * 4)   // 49152
#define GC_FLOATS (CHUNK * HH)      // 4096
#define GC_BYTES  (GC_FLOATS * 4)   // 16384

// dynamic smem layout (floats)
#define OFF_WB0   0
#define OFF_WB1   (OFF_WB0 + WB_FLOATS)
#define OFF_AGG   (OFF_WB1 + WB_FLOATS)
#define OFF_H     (OFF_AGG + HH * PAD)
#define OFF_ADJ   (OFF_H + HH * PAD)
#define OFF_NT    (OFF_ADJ + TB * NN)
#define OFF_MBAR  (OFF_NT + TB)          // 8-byte aligned (float count even)
#define SMEM_BYTES ((OFF_MBAR * 4) + 64)

__device__ float g_gm[BB * NN * HH];      // 64 MB
__device__ float g_adjt[BB * NN * NN];    // 8 MB

typedef unsigned long long u64;
typedef unsigned int u32;

__device__ __forceinline__ u64 pack2(float x) {
    u64 r; asm("mov.b64 %0, {%1, %1};" : "=l"(r) : "f"(x)); return r;
}
__device__ __forceinline__ void ffma2(u64 &d, u64 a, u64 b) {
    asm("fma.rn.f32x2 %0, %1, %2, %0;" : "+l"(d) : "l"(a), "l"(b));
}
__device__ __forceinline__ float2 unpack2(u64 a) {
    float2 f; asm("mov.b64 {%0, %1}, %2;" : "=f"(f.x), "=f"(f.y) : "l"(a)); return f;
}
__device__ __forceinline__ float fsig(float x) {
    return __fdividef(1.0f, 1.0f + __expf(-x));
}
__device__ __forceinline__ float ftanh(float x) {
    float y; asm("tanh.approx.f32 %0, %1;" : "=f"(y) : "f"(x)); return y;
}
__device__ __forceinline__ u32 s2u(const void* p) {
    u32 a;
    asm("{ .reg .u64 t; cvta.to.shared.u64 t, %1; cvt.u32.u64 %0, t; }" : "=r"(a) : "l"(p));
    return a;
}
__device__ __forceinline__ void mbar_init(u32 mb, u32 cnt) {
    asm volatile("mbarrier.init.shared.b64 [%0], %1;" :: "r"(mb), "r"(cnt) : "memory");
}
__device__ __forceinline__ void mbar_expect(u32 mb, u32 bytes) {
    asm volatile("mbarrier.arrive.expect_tx.shared.b64 _, [%0], %1;" :: "r"(mb), "r"(bytes) : "memory");
}
__device__ __forceinline__ void bulk_cp(u32 dst, const void* src, u32 bytes, u32 mb) {
    asm volatile("cp.async.bulk.shared::cta.global.mbarrier::complete_tx::bytes [%0], [%1], %2, [%3];"
                 :: "r"(dst), "l"(src), "r"(bytes), "r"(mb) : "memory");
}
__device__ __forceinline__ void mbar_wait(u32 mb, u32 parity) {
    asm volatile("{\n\t"
                 ".reg .pred P;\n"
                 "WL%=:\n\t"
                 "mbarrier.try_wait.parity.acquire.cta.shared::cta.b64 P, [%0], %1;\n\t"
                 "@!P bra WL%=;\n\t"
                 "}" :: "r"(mb), "r"(parity) : "memory");
}

__global__ void transpose_adj_kernel(const float* __restrict__ adj) {
    int idx = blockIdx.x * blockDim.x + threadIdx.x;
    if (idx < BB * NN * NN) {
        int b = idx >> 10;
        int r = idx & 1023;
        int v = r >> 5;
        int n = r & 31;
        g_adjt[idx] = adj[(b << 10) + (n << 5) + v];
    }
}

__global__ __launch_bounds__(512, 1) void logicvae_main(
    const int*   __restrict__ node_types,
    const float* __restrict__ w_ih,
    const float* __restrict__ w_hh,
    const float* __restrict__ b_ih,
    const float* __restrict__ b_hh,
    const float* __restrict__ w_gate,
    const float* __restrict__ b_gate,
    const float* __restrict__ w_map,
    const float* __restrict__ w_mu,
    const float* __restrict__ b_mu,
    const float* __restrict__ w_std,
    const float* __restrict__ b_std,
    float* __restrict__ out)
{
    extern __shared__ __align__(128) float smem[];
    float* wb0   = smem + OFF_WB0;
    float* wb1   = smem + OFF_WB1;
    float* agg_s = smem + OFF_AGG;
    float* h_s   = smem + OFF_H;
    float* adj_s = smem + OFF_ADJ;
    int*   nt_s  = (int*)(smem + OFF_NT);

    const u32 wb0u = s2u(wb0);
    const u32 wb1u = s2u(wb1);
    const u32 mb0  = s2u(smem + OFF_MBAR);
    const u32 mb1  = mb0 + 8;

    const int tid = threadIdx.x;       // 0..511
    const int j   = tid & 255;
    const int hf  = tid >> 8;
    const int hb  = hf * 8;
    const int b0  = blockIdx.x * TB;

    const float bihr = b_ih[j], bihz = b_ih[j + HH], bihn = b_ih[j + 2 * HH];
    const float bhhr = b_hh[j], bhhz = b_hh[j + HH], bhhn = b_hh[j + 2 * HH];
    const float bg   = b_gate[j];

    unsigned p0 = 0, p1 = 0;   // mbarrier phase parity trackers (uniform across threads)

    if (tid == 0) { mbar_init(mb0, 1); mbar_init(mb1, 1); }
    __syncthreads();

    // prime phase-B buffers for v=0
    if (tid == 0) {
        mbar_expect(mb0, WB_BYTES); bulk_cp(wb0u, w_hh, WB_BYTES, mb0);
        mbar_expect(mb1, WB_BYTES); bulk_cp(wb1u, w_hh + CHUNK * H3, WB_BYTES, mb1);
    }

    for (int v = 0; v < NN; v++) {
        // ---- adj column v + node types ----
        {
            int b = tid >> 5, n = tid & 31;
            adj_s[tid] = g_adjt[((b0 + b) << 10) + (v << 5) + n];
        }
        if (tid < TB) nt_s[tid] = node_types[(b0 + tid) * NN + v];

        float acc[8];
        #pragma unroll
        for (int b = 0; b < 8; b++) acc[b] = 0.0f;

        __syncthreads();

        // ---- Phase A: agg = sum_n adj * gm  (overlaps with B-chunk copies) ----
        for (int n = 0; n < v; n++) {
            float a[8];
            #pragma unroll
            for (int b = 0; b < 8; b++) a[b] = adj_s[(hb + b) * NN + n];
            float s = a[0]+a[1]+a[2]+a[3]+a[4]+a[5]+a[6]+a[7];
            if (s != 0.0f) {
                #pragma unroll
                for (int b = 0; b < 8; b++) {
                    acc[b] = fmaf(a[b],
                                  g_gm[(size_t)((b0 + hb + b) * NN + n) * HH + j],
                                  acc[b]);
                }
            }
        }
        {
            float4* a4 = (float4*)(agg_s + j * PAD + hb);
            a4[0] = make_float4(acc[0], acc[1], acc[2], acc[3]);
            a4[1] = make_float4(acc[4], acc[5], acc[6], acc[7]);
        }
        __syncthreads();

        // ---- Phase B: gh = agg @ w_hh, weights streamed through smem ----
        u64 ar2[4], az2[4], an2[4];
        #pragma unroll
        for (int i = 0; i < 4; i++) { ar2[i] = 0ull; az2[i] = 0ull; an2[i] = 0ull; }

        for (int c = 0; c < NCH; c++) {
            const float* W = (c & 1) ? wb1 : wb0;
            if (c & 1) { mbar_wait(mb1, p1); p1 ^= 1; }
            else       { mbar_wait(mb0, p0); p0 ^= 1; }
            #pragma unroll
            for (int kk = 0; kk < CHUNK; kk++) {
                const int k = c * CHUNK + kk;
                const u64 wr2 = pack2(W[kk * H3 + j]);
                const u64 wz2 = pack2(W[kk * H3 + HH + j]);
                const u64 wn2 = pack2(W[kk * H3 + 2 * HH + j]);
                const ulonglong2* p = (const ulonglong2*)(agg_s + k * PAD + hb);
                const ulonglong2 q0 = p[0], q1 = p[1];
                ffma2(ar2[0], q0.x, wr2); ffma2(ar2[1], q0.y, wr2);
                ffma2(ar2[2], q1.x, wr2); ffma2(ar2[3], q1.y, wr2);
                ffma2(az2[0], q0.x, wz2); ffma2(az2[1], q0.y, wz2);
                ffma2(az2[2], q1.x, wz2); ffma2(az2[3], q1.y, wz2);
                ffma2(an2[0], q0.x, wn2); ffma2(an2[1], q0.y, wn2);
                ffma2(an2[2], q1.x, wn2); ffma2(an2[3], q1.y, wn2);
            }
            __syncthreads();
            if (tid == 0 && c + 2 < NCH) {
                if (c & 1) { mbar_expect(mb1, WB_BYTES);
                             bulk_cp(wb1u, w_hh + (c + 2) * CHUNK * H3, WB_BYTES, mb1); }
                else       { mbar_expect(mb0, WB_BYTES);
                             bulk_cp(wb0u, w_hh + (c + 2) * CHUNK * H3, WB_BYTES, mb0); }
            }
        }

        // prime phase-C buffers (gate chunk at 0, map chunk at +GC_FLOATS)
        if (tid == 0 && v < NN - 1) {
            mbar_expect(mb0, 2 * GC_BYTES);
            bulk_cp(wb0u, w_gate, GC_BYTES, mb0);
            bulk_cp(wb0u + GC_BYTES, w_map, GC_BYTES, mb0);
            mbar_expect(mb1, 2 * GC_BYTES);
            bulk_cp(wb1u, w_gate + CHUNK * HH, GC_BYTES, mb1);
            bulk_cp(wb1u + GC_BYTES, w_map + CHUNK * HH, GC_BYTES, mb1);
        }

        // ---- GRU elementwise (x@w_ih is a one-hot row lookup) ----
        {
            float hval[8];
            #pragma unroll
            for (int i = 0; i < 4; i++) {
                const float2 fr = unpack2(ar2[i]);
                const float2 fz = unpack2(az2[i]);
                const float2 fn = unpack2(an2[i]);
                #pragma unroll
                for (int u = 0; u < 2; u++) {
                    const int b = 2 * i + u;
                    const int t = nt_s[hb + b];
                    const float gir = w_ih[t * H3 + j]          + bihr;
                    const float giz = w_ih[t * H3 + HH + j]     + bihz;
                    const float gin = w_ih[t * H3 + 2 * HH + j] + bihn;
                    const float arv = u ? fr.y : fr.x;
                    const float azv = u ? fz.y : fz.x;
                    const float anv = u ? fn.y : fn.x;
                    const float r   = fsig(gir + arv + bhhr);
                    const float z   = fsig(giz + azv + bhhz);
                    const float nn_ = ftanh(gin + r * (anv + bhhn));
                    hval[b] = (1.0f - z) * nn_ + z * acc[b];
                }
            }
            float4* h4w = (float4*)(h_s + j * PAD + hb);
            h4w[0] = make_float4(hval[0], hval[1], hval[2], hval[3]);
            h4w[1] = make_float4(hval[4], hval[5], hval[6], hval[7]);
        }
        __syncthreads();

        if (v < NN - 1) {
            // ---- Phase C: gm_v = sigmoid(h@w_gate+bg) * (h@w_map) ----
            u64 ag2[4], am2[4];
            #pragma unroll
            for (int i = 0; i < 4; i++) { ag2[i] = 0ull; am2[i] = 0ull; }

            for (int c = 0; c < NCH; c++) {
                const float* W = (c & 1) ? wb1 : wb0;
                if (c & 1) { mbar_wait(mb1, p1); p1 ^= 1; }
                else       { mbar_wait(mb0, p0); p0 ^= 1; }
                #pragma unroll
                for (int kk = 0; kk < CHUNK; kk++) {
                    const int k = c * CHUNK + kk;
                    const u64 wg2 = pack2(W[kk * HH + j]);
                    const u64 wm2 = pack2(W[GC_FLOATS + kk * HH + j]);
                    const ulonglong2* p = (const ulonglong2*)(h_s + k * PAD + hb);
                    const ulonglong2 q0 = p[0], q1 = p[1];
                    ffma2(ag2[0], q0.x, wg2); ffma2(ag2[1], q0.y, wg2);
                    ffma2(ag2[2], q1.x, wg2); ffma2(ag2[3], q1.y, wg2);
                    ffma2(am2[0], q0.x, wm2); ffma2(am2[1], q0.y, wm2);
                    ffma2(am2[2], q1.x, wm2); ffma2(am2[3], q1.y, wm2);
                }
                __syncthreads();
                if (tid == 0 && c + 2 < NCH) {
                    const int cs = (c + 2) * CHUNK * HH;
                    if (c & 1) { mbar_expect(mb1, 2 * GC_BYTES);
                                 bulk_cp(wb1u, w_gate + cs, GC_BYTES, mb1);
                                 bulk_cp(wb1u + GC_BYTES, w_map + cs, GC_BYTES, mb1); }
                    else       { mbar_expect(mb0, 2 * GC_BYTES);
                                 bulk_cp(wb0u, w_gate + cs, GC_BYTES, mb0);
                                 bulk_cp(wb0u + GC_BYTES, w_map + cs, GC_BYTES, mb0); }
                }
            }

            #pragma unroll
            for (int i = 0; i < 4; i++) {
                const float2 fg = unpack2(ag2[i]);
                const float2 fm = unpack2(am2[i]);
                const int ba = hb + 2 * i;
                g_gm[(size_t)((b0 + ba)     * NN + v) * HH + j] = fsig(fg.x + bg) * fm.x;
                g_gm[(size_t)((b0 + ba + 1) * NN + v) * HH + j] = fsig(fg.y + bg) * fm.y;
            }

            // prime next step's phase-B buffers (buffers free after last C sync)
            if (tid == 0) {
                mbar_expect(mb0, WB_BYTES); bulk_cp(wb0u, w_hh, WB_BYTES, mb0);
                mbar_expect(mb1, WB_BYTES); bulk_cp(wb1u, w_hh + CHUNK * H3, WB_BYTES, mb1);
            }
        } else {
            // ---- Final: mu = h31@w_mu+b_mu ; sigma = h31@w_std+b_std ----
            const int z   = tid & 63;
            const int grp = tid >> 6;
            const int bA  = 2 * grp, bB = 2 * grp + 1;
            float am0 = 0.f, am1 = 0.f, as0 = 0.f, as1 = 0.f;
            #pragma unroll 4
            for (int k = 0; k < HH; k++) {
                const float wm = w_mu[k * ZZ + z];
                const float ws = w_std[k * ZZ + z];
                const float h0 = h_s[k * PAD + bA];
                const float h1 = h_s[k * PAD + bB];
                am0 = fmaf(h0, wm, am0); am1 = fmaf(h1, wm, am1);
                as0 = fmaf(h0, ws, as0); as1 = fmaf(h1, ws, as1);
            }
            const float bmu = b_mu[z], bstd = b_std[z];
            out[(size_t)(b0 + bA) * ZZ + z] = am0 + bmu;
            out[(size_t)(b0 + bB) * ZZ + z] = am1 + bmu;
            out[(size_t)BB * ZZ + (size_t)(b0 + bA) * ZZ + z] = as0 + bstd;
            out[(size_t)BB * ZZ + (size_t)(b0 + bB) * ZZ + z] = as1 + bstd;
        }
    }
}

extern "C" void kernel_launch(void* const* d_in, const int* in_sizes, int n_in,
                              void* d_out, int out_size) {
    const float* adj        = (const float*)d_in[0];
    const int*   node_types = (const int*)  d_in[1];
    const float* w_ih       = (const float*)d_in[2];
    const float* w_hh       = (const float*)d_in[3];
    const float* b_ih       = (const float*)d_in[4];
    const float* b_hh       = (const float*)d_in[5];
    const float* w_gate     = (const float*)d_in[6];
    const float* b_gate     = (const float*)d_in[7];
    const float* w_map      = (const float*)d_in[8];
    const float* w_mu       = (const float*)d_in[9];
    const float* b_mu       = (const float*)d_in[10];
    const float* w_std      = (const float*)d_in[11];
    const float* b_std      = (const float*)d_in[12];
    float* out = (float*)d_out;

    cudaFuncSetAttribute(logicvae_main,
                         cudaFuncAttributeMaxDynamicSharedMemorySize, SMEM_BYTES);

    transpose_adj_kernel<<<(BB * NN * NN + 255) / 256, 256>>>(adj);

    logicvae_main<<<NCTA, 512, SMEM_BYTES>>>(node_types, w_ih, w_hh, b_ih, b_hh,
                                             w_gate, b_gate, w_map,
                                             w_mu, b_mu, w_std, b_std, out);
}

// round 6
// speedup vs baseline: 2.1889x; 1.1324x over previous
#include <cuda_runtime.h>
#include <cuda_bf16.h>
#include <cstdint>
#include <math.h>

#define BB 2048
#define NN 32
#define HH 256
#define H3 768
#define ZZ 64
#define TB 16
#define NCTA (BB / TB)   // 128
#define PAD 20
#define CHUNK 8
#define NBUF 4
#define NCH (HH / CHUNK)             // 32 chunks per segment
#define WB_FLOATS (CHUNK * H3)       // 6144 floats = 24576 B
#define WB_BYTES  (WB_FLOATS * 4)
#define GC_FLOATS (CHUNK * HH)       // 2048 floats = 8192 B
#define GC_BYTES  (GC_FLOATS * 4)
#define TOTAL_POS (63 * 32)          // 32 B-segments + 31 C-segments, 32 chunks each = 2016

// dynamic smem layout (floats)
#define OFF_WB    0
#define OFF_AGG   (OFF_WB + NBUF * WB_FLOATS)      // 24576
#define OFF_H     (OFF_AGG + HH * PAD)
#define OFF_WIH   (OFF_H + HH * PAD)
#define OFF_ADJ   (OFF_WIH + 10 * H3)
#define OFF_NT    (OFF_ADJ + TB * NN)
#define OFF_MBAR  (OFF_NT + TB)                    // even float count -> 8B aligned
#define SMEM_BYTES ((OFF_MBAR + 16) * 4 + 64)

__device__ float g_gm[BB * NN * HH];      // 64 MB
__device__ float g_adjt[BB * NN * NN];    // 8 MB

typedef unsigned long long u64;
typedef unsigned int u32;

__device__ __forceinline__ u64 pack2(float x) {
    u64 r; asm("mov.b64 %0, {%1, %1};" : "=l"(r) : "f"(x)); return r;
}
__device__ __forceinline__ void ffma2(u64 &d, u64 a, u64 b) {
    asm("fma.rn.f32x2 %0, %1, %2, %0;" : "+l"(d) : "l"(a), "l"(b));
}
__device__ __forceinline__ float2 unpack2(u64 a) {
    float2 f; asm("mov.b64 {%0, %1}, %2;" : "=f"(f.x), "=f"(f.y) : "l"(a)); return f;
}
__device__ __forceinline__ float fsig(float x) {
    return __fdividef(1.0f, 1.0f + __expf(-x));
}
__device__ __forceinline__ float ftanh(float x) {
    float y; asm("tanh.approx.f32 %0, %1;" : "=f"(y) : "f"(x)); return y;
}
__device__ __forceinline__ u32 s2u(const void* p) {
    u32 a;
    asm("{ .reg .u64 t; cvta.to.shared.u64 t, %1; cvt.u32.u64 %0, t; }" : "=r"(a) : "l"(p));
    return a;
}
__device__ __forceinline__ void mbar_init(u32 mb, u32 cnt) {
    asm volatile("mbarrier.init.shared.b64 [%0], %1;" :: "r"(mb), "r"(cnt) : "memory");
}
__device__ __forceinline__ void mbar_expect(u32 mb, u32 bytes) {
    asm volatile("mbarrier.arrive.expect_tx.shared.b64 _, [%0], %1;" :: "r"(mb), "r"(bytes) : "memory");
}
__device__ __forceinline__ void mbar_arrive(u32 mb) {
    asm volatile("mbarrier.arrive.release.cta.shared::cta.b64 _, [%0];" :: "r"(mb) : "memory");
}
__device__ __forceinline__ void bulk_cp(u32 dst, const void* src, u32 bytes, u32 mb) {
    asm volatile("cp.async.bulk.shared::cta.global.mbarrier::complete_tx::bytes [%0], [%1], %2, [%3];"
                 :: "r"(dst), "l"(src), "r"(bytes), "r"(mb) : "memory");
}
__device__ __forceinline__ void mbar_wait(u32 mb, u32 parity) {
    asm volatile("{\n\t"
                 ".reg .pred P;\n"
                 "WL%=:\n\t"
                 "mbarrier.try_wait.parity.acquire.cta.shared::cta.b64 P, [%0], %1;\n\t"
                 "@!P bra WL%=;\n\t"
                 "}" :: "r"(mb), "r"(parity) : "memory");
}

__global__ void transpose_adj_kernel(const float* __restrict__ adj) {
    int idx = blockIdx.x * blockDim.x + threadIdx.x;
    if (idx < BB * NN * NN) {
        int b = idx >> 10;
        int r = idx & 1023;
        int v = r >> 5;
        int n = r & 31;
        g_adjt[idx] = adj[(b << 10) + (n << 5) + v];
    }
}

// issue the TMA copy for global stream position `pos` into buffer (pos & 3)
__device__ __forceinline__ void issue_copy(
    int pos, u32 wbu, u32 mb_full_base,
    const float* __restrict__ w_hh,
    const float* __restrict__ w_gate,
    const float* __restrict__ w_map)
{
    const int seg = pos >> 5;
    const int rem = pos & 31;
    const int buf = pos & (NBUF - 1);
    const u32 dst = wbu + (u32)buf * WB_BYTES;
    const u32 mb  = mb_full_base + (u32)buf * 8;
    if (seg & 1) {   // C segment: gate + map chunk
        mbar_expect(mb, 2 * GC_BYTES);
        bulk_cp(dst, w_gate + rem * GC_FLOATS, GC_BYTES, mb);
        bulk_cp(dst + GC_BYTES, w_map + rem * GC_FLOATS, GC_BYTES, mb);
    } else {         // B segment: w_hh chunk
        mbar_expect(mb, WB_BYTES);
        bulk_cp(dst, w_hh + rem * WB_FLOATS, WB_BYTES, mb);
    }
}

__global__ __launch_bounds__(512, 1) void logicvae_main(
    const int*   __restrict__ node_types,
    const float* __restrict__ w_ih,
    const float* __restrict__ w_hh,
    const float* __restrict__ b_ih,
    const float* __restrict__ b_hh,
    const float* __restrict__ w_gate,
    const float* __restrict__ b_gate,
    const float* __restrict__ w_map,
    const float* __restrict__ w_mu,
    const float* __restrict__ b_mu,
    const float* __restrict__ w_std,
    const float* __restrict__ b_std,
    float* __restrict__ out)
{
    extern __shared__ __align__(128) float smem[];
    float* wb    = smem + OFF_WB;
    float* agg_s = smem + OFF_AGG;
    float* h_s   = smem + OFF_H;
    float* wih_s = smem + OFF_WIH;
    float* adj_s = smem + OFF_ADJ;
    int*   nt_s  = (int*)(smem + OFF_NT);

    const u32 wbu      = s2u(wb);
    const u32 mb_full  = s2u(smem + OFF_MBAR);        // 4 full barriers
    const u32 mb_empty = mb_full + NBUF * 8;          // 4 empty barriers

    const int tid = threadIdx.x;       // 0..511
    const int j   = tid & 255;
    const int hb  = (tid >> 8) * 8;
    const int b0  = blockIdx.x * TB;

    const float bihr = b_ih[j], bihz = b_ih[j + HH], bihn = b_ih[j + 2 * HH];
    const float bhhr = b_hh[j], bhhz = b_hh[j + HH], bhhn = b_hh[j + 2 * HH];
    const float bg   = b_gate[j];

    if (tid == 0) {
        #pragma unroll
        for (int i = 0; i < NBUF; i++) {
            mbar_init(mb_full + i * 8, 1);
            mbar_init(mb_empty + i * 8, 512);
        }
    }
    // stage w_ih into smem once (persistent)
    for (int idx = tid; idx < 10 * H3; idx += 512) wih_s[idx] = w_ih[idx];
    __syncthreads();

    // prime ring: stream positions 0..3
    if (tid == 0) {
        #pragma unroll
        for (int p = 0; p < NBUF; p++) issue_copy(p, wbu, mb_full, w_hh, w_gate, w_map);
    }

    for (int v = 0; v < NN; v++) {
        // ---- adj column v + node types ----
        {
            int b = tid >> 5, n = tid & 31;
            adj_s[tid] = g_adjt[((b0 + b) << 10) + (v << 5) + n];
        }
        if (tid < TB) nt_s[tid] = node_types[(b0 + tid) * NN + v];

        float acc[8];
        #pragma unroll
        for (int b = 0; b < 8; b++) acc[b] = 0.0f;

        __syncthreads();   // BAR 1: adj_s / nt_s

        // ---- Phase A: agg = sum_n adj * gm ----
        for (int n = 0; n < v; n++) {
            float a[8];
            #pragma unroll
            for (int b = 0; b < 8; b++) a[b] = adj_s[(hb + b) * NN + n];
            float s = a[0]+a[1]+a[2]+a[3]+a[4]+a[5]+a[6]+a[7];
            if (s != 0.0f) {
                #pragma unroll
                for (int b = 0; b < 8; b++) {
                    acc[b] = fmaf(a[b],
                                  g_gm[(size_t)((b0 + hb + b) * NN + n) * HH + j],
                                  acc[b]);
                }
            }
        }
        {
            float4* a4 = (float4*)(agg_s + j * PAD + hb);
            a4[0] = make_float4(acc[0], acc[1], acc[2], acc[3]);
            a4[1] = make_float4(acc[4], acc[5], acc[6], acc[7]);
        }
        __syncthreads();   // BAR 2: agg_s

        // ---- Phase B: gh = agg @ w_hh, ring-streamed weights, no CTA barriers ----
        u64 ar2[4], az2[4], an2[4];
        #pragma unroll
        for (int i = 0; i < 4; i++) { ar2[i] = 0ull; az2[i] = 0ull; an2[i] = 0ull; }

        for (int c = 0; c < NCH; c++) {
            const int pos = 64 * v + c;
            const int buf = pos & (NBUF - 1);
            const u32 par = (u32)(pos >> 2) & 1;
            mbar_wait(mb_full + buf * 8, par);
            const float* W = wb + buf * WB_FLOATS;
            #pragma unroll
            for (int kk = 0; kk < CHUNK; kk++) {
                const int k = c * CHUNK + kk;
                const u64 wr2 = pack2(W[kk * H3 + j]);
                const u64 wz2 = pack2(W[kk * H3 + HH + j]);
                const u64 wn2 = pack2(W[kk * H3 + 2 * HH + j]);
                const ulonglong2* p = (const ulonglong2*)(agg_s + k * PAD + hb);
                const ulonglong2 q0 = p[0], q1 = p[1];
                ffma2(ar2[0], q0.x, wr2); ffma2(ar2[1], q0.y, wr2);
                ffma2(ar2[2], q1.x, wr2); ffma2(ar2[3], q1.y, wr2);
                ffma2(az2[0], q0.x, wz2); ffma2(az2[1], q0.y, wz2);
                ffma2(az2[2], q1.x, wz2); ffma2(az2[3], q1.y, wz2);
                ffma2(an2[0], q0.x, wn2); ffma2(an2[1], q0.y, wn2);
                ffma2(an2[2], q1.x, wn2); ffma2(an2[3], q1.y, wn2);
            }
            mbar_arrive(mb_empty + buf * 8);
            if (tid == 0 && pos + NBUF < TOTAL_POS) {
                mbar_wait(mb_empty + buf * 8, par);
                issue_copy(pos + NBUF, wbu, mb_full, w_hh, w_gate, w_map);
            }
        }

        // ---- GRU elementwise (x@w_ih one-hot lookup from smem) ----
        {
            float hval[8];
            #pragma unroll
            for (int i = 0; i < 4; i++) {
                const float2 fr = unpack2(ar2[i]);
                const float2 fz = unpack2(az2[i]);
                const float2 fn = unpack2(an2[i]);
                #pragma unroll
                for (int u = 0; u < 2; u++) {
                    const int b = 2 * i + u;
                    const int t = nt_s[hb + b];
                    const float gir = wih_s[t * H3 + j]          + bihr;
                    const float giz = wih_s[t * H3 + HH + j]     + bihz;
                    const float gin = wih_s[t * H3 + 2 * HH + j] + bihn;
                    const float arv = u ? fr.y : fr.x;
                    const float azv = u ? fz.y : fz.x;
                    const float anv = u ? fn.y : fn.x;
                    const float r   = fsig(gir + arv + bhhr);
                    const float z   = fsig(giz + azv + bhhz);
                    const float nn_ = ftanh(gin + r * (anv + bhhn));
                    hval[b] = (1.0f - z) * nn_ + z * acc[b];
                }
            }
            float4* h4w = (float4*)(h_s + j * PAD + hb);
            h4w[0] = make_float4(hval[0], hval[1], hval[2], hval[3]);
            h4w[1] = make_float4(hval[4], hval[5], hval[6], hval[7]);
        }
        __syncthreads();   // BAR 3: h_s

        if (v < NN - 1) {
            // ---- Phase C: gm_v = sigmoid(h@w_gate+bg) * (h@w_map) ----
            u64 ag2[4], am2[4];
            #pragma unroll
            for (int i = 0; i < 4; i++) { ag2[i] = 0ull; am2[i] = 0ull; }

            for (int c = 0; c < NCH; c++) {
                const int pos = 64 * v + 32 + c;
                const int buf = pos & (NBUF - 1);
                const u32 par = (u32)(pos >> 2) & 1;
                mbar_wait(mb_full + buf * 8, par);
                const float* W = wb + buf * WB_FLOATS;
                #pragma unroll
                for (int kk = 0; kk < CHUNK; kk++) {
                    const int k = c * CHUNK + kk;
                    const u64 wg2 = pack2(W[kk * HH + j]);
                    const u64 wm2 = pack2(W[GC_FLOATS + kk * HH + j]);
                    const ulonglong2* p = (const ulonglong2*)(h_s + k * PAD + hb);
                    const ulonglong2 q0 = p[0], q1 = p[1];
                    ffma2(ag2[0], q0.x, wg2); ffma2(ag2[1], q0.y, wg2);
                    ffma2(ag2[2], q1.x, wg2); ffma2(ag2[3], q1.y, wg2);
                    ffma2(am2[0], q0.x, wm2); ffma2(am2[1], q0.y, wm2);
                    ffma2(am2[2], q1.x, wm2); ffma2(am2[3], q1.y, wm2);
                }
                mbar_arrive(mb_empty + buf * 8);
                if (tid == 0 && pos + NBUF < TOTAL_POS) {
                    mbar_wait(mb_empty + buf * 8, par);
                    issue_copy(pos + NBUF, wbu, mb_full, w_hh, w_gate, w_map);
                }
            }

            #pragma unroll
            for (int i = 0; i < 4; i++) {
                const float2 fg = unpack2(ag2[i]);
                const float2 fm = unpack2(am2[i]);
                const int ba = hb + 2 * i;
                g_gm[(size_t)((b0 + ba)     * NN + v) * HH + j] = fsig(fg.x + bg) * fm.x;
                g_gm[(size_t)((b0 + ba + 1) * NN + v) * HH + j] = fsig(fg.y + bg) * fm.y;
            }
        } else {
            // ---- Final: mu = h31@w_mu+b_mu ; sigma = h31@w_std+b_std ----
            const int z   = tid & 63;
            const int grp = tid >> 6;
            const int bA  = 2 * grp, bB = 2 * grp + 1;
            float am0 = 0.f, am1 = 0.f, as0 = 0.f, as1 = 0.f;
            #pragma unroll 4
            for (int k = 0; k < HH; k++) {
                const float wm = w_mu[k * ZZ + z];
                const float ws = w_std[k * ZZ + z];
                const float h0 = h_s[k * PAD + bA];
                const float h1 = h_s[k * PAD + bB];
                am0 = fmaf(h0, wm, am0); am1 = fmaf(h1, wm, am1);
                as0 = fmaf(h0, ws, as0); as1 = fmaf(h1, ws, as1);
            }
            const float bmu = b_mu[z], bstd = b_std[z];
            out[(size_t)(b0 + bA) * ZZ + z] = am0 + bmu;
            out[(size_t)(b0 + bB) * ZZ + z] = am1 + bmu;
            out[(size_t)BB * ZZ + (size_t)(b0 + bA) * ZZ + z] = as0 + bstd;
            out[(size_t)BB * ZZ + (size_t)(b0 + bB) * ZZ + z] = as1 + bstd;
        }
    }
}

extern "C" void kernel_launch(void* const* d_in, const int* in_sizes, int n_in,
                              void* d_out, int out_size) {
    const float* adj        = (const float*)d_in[0];
    const int*   node_types = (const int*)  d_in[1];
    const float* w_ih       = (const float*)d_in[2];
    const float* w_hh       = (const float*)d_in[3];
    const float* b_ih       = (const float*)d_in[4];
    const float* b_hh       = (const float*)d_in[5];
    const float* w_gate     = (const float*)d_in[6];
    const float* b_gate     = (const float*)d_in[7];
    const float* w_map      = (const float*)d_in[8];
    const float* w_mu       = (const float*)d_in[9];
    const float* b_mu       = (const float*)d_in[10];
    const float* w_std      = (const float*)d_in[11];
    const float* b_std      = (const float*)d_in[12];
    float* out = (float*)d_out;

    cudaFuncSetAttribute(logicvae_main,
                         cudaFuncAttributeMaxDynamicSharedMemorySize, SMEM_BYTES);

    transpose_adj_kernel<<<(BB * NN * NN + 255) / 256, 256>>>(adj);

    logicvae_main<<<NCTA, 512, SMEM_BYTES>>>(node_types, w_ih, w_hh, b_ih, b_hh,
                                             w_gate, b_gate, w_map,
                                             w_mu, b_mu, w_std, b_std, out);
}